// round 16
// baseline (speedup 1.0000x reference)
#include <cuda_runtime.h>
#include <cuda_bf16.h>
#include <cstdint>

#define N_NODES 100000
#define N_EDGES 1200000
#define D 64
#define KEEP_PROB 0.7f
#define SCAN_CHUNK 2048
#define NUM_SBLK ((N_NODES + SCAN_CHUNK - 1) / SCAN_CHUNK)  // 49

typedef unsigned long long ull;

// ---- packed f32x2 helpers (Blackwell FFMA2 via PTX; ptxas won't auto-fuse) ----
__device__ __forceinline__ ull pk2(float a, float b) {
    ull r; asm("mov.b64 %0, {%1, %2};" : "=l"(r) : "f"(a), "f"(b)); return r;
}
__device__ __forceinline__ ull fma2(ull a, ull b, ull c) {
    ull d; asm("fma.rn.f32x2 %0, %1, %2, %3;" : "=l"(d) : "l"(a), "l"(b), "l"(c)); return d;
}
__device__ __forceinline__ ull add2(ull a, ull b) {
    ull d; asm("add.rn.f32x2 %0, %1, %2;" : "=l"(d) : "l"(a), "l"(b)); return d;
}
__device__ __forceinline__ ull mul2(ull a, ull b) {
    ull d; asm("mul.rn.f32x2 %0, %1, %2;" : "=l"(d) : "l"(a), "l"(b)); return d;
}
__device__ __forceinline__ void upk2(ull v, float& lo, float& hi) {
    asm("mov.b64 {%0, %1}, %2;" : "=f"(lo), "=f"(hi) : "l"(v));
}

// ---------------------------------------------------------------------------
// Scratch (__device__ globals; zero-initialized at module load).
// Packed: low 32 bits = layer 0, high 32 bits = layer 1.
// INVARIANT at every kernel_launch entry: g_cnt == 0, g_flag == 0.
//   - initial state: CUDA zero-inits device globals
//   - each run: scan_fused re-zeros g_cnt after reading; scatter resets g_flag
// ---------------------------------------------------------------------------
__device__ ull  g_cnt[N_NODES];
__device__ ull  g_off[N_NODES + 1];
__device__ ull  g_cur[N_NODES];
__device__ int  g_flag[NUM_SBLK];   // 0=none, 1=aggregate ready, 2=inclusive ready
__device__ ull  g_aggv[NUM_SBLK];
__device__ ull  g_incv[NUM_SBLK];
__device__ int2 g_e0[N_EDGES];
__device__ int2 g_e1[N_EDGES];
__device__ float g_x1[(size_t)N_NODES * D];

// ---------------------------------------------------------------------------
// 1) count kept edges; 2 edges per thread (split-half, both coalesced) for
//    atomic MLP=2.
// ---------------------------------------------------------------------------
__global__ void count_kernel(const int* __restrict__ rows,
                             const float* __restrict__ du) {
    const int H = N_EDGES / 2;
    int t = blockIdx.x * blockDim.x + threadIdx.x;
    if (t >= H) return;
    int ea = t, eb = t + H;

    float a0 = du[ea], a1 = du[N_EDGES + ea];
    float b0 = du[eb], b1 = du[N_EDGES + eb];
    ull adda = (a0 + KEEP_PROB >= 1.0f ? 1ULL : 0ULL) +
               (a1 + KEEP_PROB >= 1.0f ? (1ULL << 32) : 0ULL);
    ull addb = (b0 + KEEP_PROB >= 1.0f ? 1ULL : 0ULL) +
               (b1 + KEEP_PROB >= 1.0f ? (1ULL << 32) : 0ULL);
    int ra = rows[ea], rb = rows[eb];
    if (adda) atomicAdd(&g_cnt[ra], adda);
    if (addb) atomicAdd(&g_cnt[rb], addb);
}

// ---------------------------------------------------------------------------
// 2) single-kernel exclusive scan (decoupled lookback, 49 resident blocks)
//    Also zeros g_cnt for the next run and initializes the cursors.
// ---------------------------------------------------------------------------
__global__ void __launch_bounds__(256) scan_fused_kernel() {
    __shared__ ull wt[8];
    __shared__ ull blk_exc;
    int tid = threadIdx.x;
    int lane = tid & 31, wid = tid >> 5;
    int bid = blockIdx.x;
    int base = bid * SCAN_CHUNK + tid * 8;

    ull v[8]; ull sum = 0ULL;
    #pragma unroll
    for (int j = 0; j < 8; j++) {
        int idx = base + j;
        if (idx < N_NODES) {
            v[j] = g_cnt[idx];
            g_cnt[idx] = 0ULL;          // re-zero for next run
        } else v[j] = 0ULL;
        sum += v[j];
    }
    ull s = sum;
    #pragma unroll
    for (int o = 1; o < 32; o <<= 1) {
        ull t = __shfl_up_sync(0xffffffffu, s, o);
        if (lane >= o) s += t;
    }
    if (lane == 31) wt[wid] = s;
    __syncthreads();

    if (tid == 0) {
        ull r = 0ULL;
        #pragma unroll
        for (int k = 0; k < 8; k++) { ull t = wt[k]; wt[k] = r; r += t; }
        ull wtot = r;

        volatile int* vf = g_flag;
        volatile ull* va = g_aggv;
        volatile ull* vi = g_incv;
        if (bid == 0) {
            vi[0] = wtot;
            __threadfence();
            vf[0] = 2;
            blk_exc = 0ULL;
        } else {
            va[bid] = wtot;
            __threadfence();
            vf[bid] = 1;
            ull exc = 0ULL;
            int j = bid - 1;
            while (true) {
                int f;
                do { f = vf[j]; } while (f == 0);
                if (f == 2) { exc += vi[j]; break; }
                exc += va[j];
                j--;
            }
            vi[bid] = exc + wtot;
            __threadfence();
            vf[bid] = 2;
            blk_exc = exc;
        }
    }
    __syncthreads();

    ull run = blk_exc + wt[wid] + (s - sum);
    #pragma unroll
    for (int j = 0; j < 8; j++) {
        int idx = base + j;
        if (idx < N_NODES) {
            g_off[idx] = run;
            g_cur[idx] = run;
            if (idx == N_NODES - 1) g_off[N_NODES] = run + v[j];
        }
        run += v[j];
    }
}

// ---------------------------------------------------------------------------
// 3) scatter kept edges; 2 edges per thread (split-half) for atomic MLP=2;
//    also resets lookback flags.
// ---------------------------------------------------------------------------
__global__ void scatter_kernel(const int* __restrict__ rows,
                               const int* __restrict__ cols,
                               const float* __restrict__ vals,
                               const float* __restrict__ du) {
    if (blockIdx.x == 0 && threadIdx.x < NUM_SBLK) g_flag[threadIdx.x] = 0;
    const int H = N_EDGES / 2;
    int t = blockIdx.x * blockDim.x + threadIdx.x;
    if (t >= H) return;

    #pragma unroll
    for (int half = 0; half < 2; half++) {
        int e = t + half * H;
        float u0 = du[e];
        float u1 = du[N_EDGES + e];
        bool k0 = (u0 + KEEP_PROB >= 1.0f);
        bool k1 = (u1 + KEEP_PROB >= 1.0f);
        if (k0 || k1) {
            int r = rows[e];
            int c = cols[e];
            float v = vals[e] / KEEP_PROB;
            ull add = (k0 ? 1ULL : 0ULL) + (k1 ? (1ULL << 32) : 0ULL);
            ull old = atomicAdd(&g_cur[r], add);
            int2 pay = make_int2(c, __float_as_int(v));
            if (k0) g_e0[(int)(old & 0xffffffffULL)] = pay;
            if (k1) g_e1[(int)(old >> 32)] = pay;
        }
    }
}

// ---------------------------------------------------------------------------
// FC v4: 8x8 register tiles, 128 threads / 128 nodes per block, dynamic smem.
// Per k-step each thread: 64 B LDS for 64 FMAs (1 B/FMA, half of v3).
// out[n][d] = sum_k emb[n][k] * W[d][k] + b[d]
// ---------------------------------------------------------------------------
#define FC4_SMEM ((64 * 68 + 64 * 132) * 4)   // Wt + et = 51200 B

__global__ void __launch_bounds__(128) fc4_kernel(
        const float* __restrict__ emb,
        const float* __restrict__ W,
        const float* __restrict__ b,
        float* __restrict__ out) {
    extern __shared__ float sm[];
    float* Wt = sm;                 // Wt[k*68 + d]
    float* et = sm + 64 * 68;       // et[k*132 + node]

    int tid = threadIdx.x;
    int n0 = blockIdx.x * 128;

    // load W (coalesced) -> k-major
    #pragma unroll
    for (int i = tid; i < 4096; i += 128) {
        int r = i >> 6, k = i & 63;
        Wt[k * 68 + r] = W[i];
    }
    // load emb tile (coalesced) -> k-major
    #pragma unroll
    for (int i = tid; i < 8192; i += 128) {
        int node = i >> 6, k = i & 63;
        int n = n0 + node;
        et[k * 132 + node] = (n < N_NODES) ? emb[(size_t)n * 64 + k] : 0.0f;
    }
    __syncthreads();

    int tx = tid & 7;          // dim group: d0 = 8*tx
    int ty = tid >> 3;         // node group: r0 = 8*ty (0..15)
    int d0 = tx * 8;
    int r0 = ty * 8;

    ull acc[8][4];
    #pragma unroll
    for (int a = 0; a < 8; a++)
        #pragma unroll
        for (int c = 0; c < 4; c++) acc[a][c] = 0ULL;

    #pragma unroll 2
    for (int k = 0; k < 64; k++) {
        const float* ek = &et[k * 132 + r0];
        const float* wk = &Wt[k * 68 + d0];
        float4 e0 = *reinterpret_cast<const float4*>(ek);
        float4 e1 = *reinterpret_cast<const float4*>(ek + 4);
        float4 w0 = *reinterpret_cast<const float4*>(wk);
        float4 w1 = *reinterpret_cast<const float4*>(wk + 4);
        ull wp[4];
        wp[0] = pk2(w0.x, w0.y);
        wp[1] = pk2(w0.z, w0.w);
        wp[2] = pk2(w1.x, w1.y);
        wp[3] = pk2(w1.z, w1.w);
        float ev[8] = {e0.x, e0.y, e0.z, e0.w, e1.x, e1.y, e1.z, e1.w};
        #pragma unroll
        for (int a = 0; a < 8; a++) {
            ull e2 = pk2(ev[a], ev[a]);
            #pragma unroll
            for (int c = 0; c < 4; c++)
                acc[a][c] = fma2(e2, wp[c], acc[a][c]);
        }
    }

    float bv[8];
    #pragma unroll
    for (int c = 0; c < 8; c++) bv[c] = b[d0 + c];

    #pragma unroll
    for (int a = 0; a < 8; a++) {
        int n = n0 + r0 + a;
        if (n < N_NODES) {
            float o[8];
            upk2(acc[a][0], o[0], o[1]);
            upk2(acc[a][1], o[2], o[3]);
            upk2(acc[a][2], o[4], o[5]);
            upk2(acc[a][3], o[6], o[7]);
            float4 lo = make_float4(o[0] + bv[0], o[1] + bv[1],
                                    o[2] + bv[2], o[3] + bv[3]);
            float4 hi = make_float4(o[4] + bv[4], o[5] + bv[5],
                                    o[6] + bv[6], o[7] + bv[7]);
            float* dst = &out[(size_t)n * 64 + d0];
            *reinterpret_cast<float4*>(dst) = lo;
            *reinterpret_cast<float4*>(dst + 4) = hi;
        }
    }
}

// ---------------------------------------------------------------------------
// CSR SpMM consume v4 (round-12 winner, unchanged): ONE WARP per TWO nodes,
// lane owns 2 dims (f32x2), joint walk of both edge lists for gather MLP.
// ---------------------------------------------------------------------------
template <int LAYER>
__global__ void __launch_bounds__(256) csr_spmm4_kernel(
        const float* __restrict__ x_ext,
        float* __restrict__ out) {
    int warp = threadIdx.x >> 5;
    int lane = threadIdx.x & 31;
    int n0 = blockIdx.x * 16 + warp * 2;
    int n1 = n0 + 1;

    const float* __restrict__ xf = (LAYER == 0) ? x_ext : g_x1;
    const ull* __restrict__ x2 = reinterpret_cast<const ull*>(xf);
    const int2* __restrict__ ed = (LAYER == 0) ? g_e0 : g_e1;

    ull oo0 = g_off[n0];
    ull oo1 = g_off[n1];
    ull oo2 = g_off[n1 + 1];
    int s0, e0, s1, e1;
    if (LAYER == 0) {
        s0 = (int)(oo0 & 0xffffffffULL); e0 = (int)(oo1 & 0xffffffffULL);
        s1 = e0;                         e1 = (int)(oo2 & 0xffffffffULL);
    } else {
        s0 = (int)(oo0 >> 32); e0 = (int)(oo1 >> 32);
        s1 = e0;               e1 = (int)(oo2 >> 32);
    }

    ull acc0 = 0ULL, acc1 = 0ULL;
    int i0 = s0, i1 = s1;

    while (i0 + 2 <= e0 && i1 + 2 <= e1) {
        int2 a0 = ed[i0];
        int2 a1 = ed[i0 + 1];
        int2 b0 = ed[i1];
        int2 b1 = ed[i1 + 1];
        ull xa0 = x2[a0.x * 32 + lane];
        ull xa1 = x2[a1.x * 32 + lane];
        ull xb0 = x2[b0.x * 32 + lane];
        ull xb1 = x2[b1.x * 32 + lane];
        acc0 = fma2(pk2(__int_as_float(a0.y), __int_as_float(a0.y)), xa0, acc0);
        acc0 = fma2(pk2(__int_as_float(a1.y), __int_as_float(a1.y)), xa1, acc0);
        acc1 = fma2(pk2(__int_as_float(b0.y), __int_as_float(b0.y)), xb0, acc1);
        acc1 = fma2(pk2(__int_as_float(b1.y), __int_as_float(b1.y)), xb1, acc1);
        i0 += 2; i1 += 2;
    }
    for (; i0 + 4 <= e0; i0 += 4) {
        int2 p0 = ed[i0];
        int2 p1 = ed[i0 + 1];
        int2 p2 = ed[i0 + 2];
        int2 p3 = ed[i0 + 3];
        ull x0 = x2[p0.x * 32 + lane];
        ull x1 = x2[p1.x * 32 + lane];
        ull x2v = x2[p2.x * 32 + lane];
        ull x3 = x2[p3.x * 32 + lane];
        acc0 = fma2(pk2(__int_as_float(p0.y), __int_as_float(p0.y)), x0, acc0);
        acc0 = fma2(pk2(__int_as_float(p1.y), __int_as_float(p1.y)), x1, acc0);
        acc0 = fma2(pk2(__int_as_float(p2.y), __int_as_float(p2.y)), x2v, acc0);
        acc0 = fma2(pk2(__int_as_float(p3.y), __int_as_float(p3.y)), x3, acc0);
    }
    for (; i0 < e0; i0++) {
        int2 p = ed[i0];
        float v = __int_as_float(p.y);
        acc0 = fma2(pk2(v, v), x2[p.x * 32 + lane], acc0);
    }
    for (; i1 + 4 <= e1; i1 += 4) {
        int2 p0 = ed[i1];
        int2 p1 = ed[i1 + 1];
        int2 p2 = ed[i1 + 2];
        int2 p3 = ed[i1 + 3];
        ull x0 = x2[p0.x * 32 + lane];
        ull x1 = x2[p1.x * 32 + lane];
        ull x2v = x2[p2.x * 32 + lane];
        ull x3 = x2[p3.x * 32 + lane];
        acc1 = fma2(pk2(__int_as_float(p0.y), __int_as_float(p0.y)), x0, acc1);
        acc1 = fma2(pk2(__int_as_float(p1.y), __int_as_float(p1.y)), x1, acc1);
        acc1 = fma2(pk2(__int_as_float(p2.y), __int_as_float(p2.y)), x2v, acc1);
        acc1 = fma2(pk2(__int_as_float(p3.y), __int_as_float(p3.y)), x3, acc1);
    }
    for (; i1 < e1; i1++) {
        int2 p = ed[i1];
        float v = __int_as_float(p.y);
        acc1 = fma2(pk2(v, v), x2[p.x * 32 + lane], acc1);
    }

    size_t idx0 = (size_t)n0 * 32 + lane;
    size_t idx1 = (size_t)n1 * 32 + lane;
    if (LAYER == 0) {
        ull* x1o = reinterpret_cast<ull*>(g_x1);
        x1o[idx0] = acc0;
        x1o[idx1] = acc1;
    } else {
        ull* o2 = reinterpret_cast<ull*>(out);
        const float third = 1.0f / 3.0f;
        ull th = pk2(third, third);
        ull sum0 = add2(add2(o2[idx0], x2[idx0]), acc0);
        ull sum1 = add2(add2(o2[idx1], x2[idx1]), acc1);
        o2[idx0] = mul2(sum0, th);
        o2[idx1] = mul2(sum1, th);
    }
}

// ---------------------------------------------------------------------------
extern "C" void kernel_launch(void* const* d_in, const int* in_sizes, int n_in,
                              void* d_out, int out_size) {
    const float* all_emb = (const float*)d_in[0];
    const float* W       = (const float*)d_in[1];
    const float* b       = (const float*)d_in[2];
    const float* vals    = (const float*)d_in[3];
    const float* drop_u  = (const float*)d_in[4];
    const int*   rows    = (const int*)d_in[5];
    const int*   cols    = (const int*)d_in[6];
    float* out = (float*)d_out;

    static bool attr_done = false;
    if (!attr_done) {
        cudaFuncSetAttribute(fc4_kernel,
                             cudaFuncAttributeMaxDynamicSharedMemorySize,
                             FC4_SMEM);
        attr_done = true;
    }

    const int HALF_BLOCKS = (N_EDGES / 2 + 255) / 256;   // 2344

    // CSR build (both layers at once, packed u64) — 3 launches
    count_kernel<<<HALF_BLOCKS, 256>>>(rows, drop_u);
    scan_fused_kernel<<<NUM_SBLK, 256>>>();
    scatter_kernel<<<HALF_BLOCKS, 256>>>(rows, cols, vals, drop_u);

    // fc -> out (unscaled), 8x8 register tiles + FFMA2
    fc4_kernel<<<(N_NODES + 127) / 128, 128, FC4_SMEM>>>(all_emb, W, b, out);

    // layer 0: g_x1 = A0 @ all_emb
    csr_spmm4_kernel<0><<<N_NODES / 16, 256>>>(all_emb, out);
    // layer 1 + fused finalize: out = (fc + x1 + A1 @ x1) / 3
    csr_spmm4_kernel<1><<<N_NODES / 16, 256>>>(nullptr, out);
}